// round 15
// baseline (speedup 1.0000x reference)
#include <cuda_runtime.h>
#include <cuda_bf16.h>
#include <math.h>
#include <stdint.h>

#define NTOK 98
#define CDIM 256
#define NHEAD 8
#define DH 32
#define MAXB 2048
#define MAXM (MAXB * NTOK)
#define MAXNW 64

// scratch (no allocs allowed -> device globals)
__device__ __nv_bfloat16 g_xh[(size_t)MAXM * CDIM];
__device__ __nv_bfloat16 g_xl[(size_t)MAXM * CDIM];
__device__ __nv_bfloat16 g_qkvh[(size_t)MAXM * 3 * CDIM];   // qkv hi [B*N,768]
__device__ __nv_bfloat16 g_qkvl[(size_t)MAXM * 3 * CDIM];   // qkv lo
__device__ __nv_bfloat16 g_ah[(size_t)MAXM * CDIM];         // attn out hi
__device__ __nv_bfloat16 g_al[(size_t)MAXM * CDIM];         // attn out lo
__device__ __nv_bfloat16 g_wqh[CDIM * 3 * CDIM];
__device__ __nv_bfloat16 g_wql[CDIM * 3 * CDIM];
__device__ __nv_bfloat16 g_wph[CDIM * CDIM];
__device__ __nv_bfloat16 g_wpl[CDIM * CDIM];
__device__ float g_bm[(size_t)MAXNW * NHEAD * NTOK * 100];  // bias+mask slabs

extern __shared__ unsigned char smem_raw[];

// ===========================================================================
// helpers
// ===========================================================================
__device__ __forceinline__ uint32_t smem_u32(const void* p) {
    return (uint32_t)__cvta_generic_to_shared(p);
}
__device__ __forceinline__ void ldsm_x4(uint32_t* r, uint32_t a) {
    asm volatile("ldmatrix.sync.aligned.m8n8.x4.shared.b16 {%0,%1,%2,%3},[%4];"
                 : "=r"(r[0]), "=r"(r[1]), "=r"(r[2]), "=r"(r[3]) : "r"(a));
}
__device__ __forceinline__ void ldsm_x4t(uint32_t* r, uint32_t a) {
    asm volatile("ldmatrix.sync.aligned.m8n8.x4.trans.shared.b16 {%0,%1,%2,%3},[%4];"
                 : "=r"(r[0]), "=r"(r[1]), "=r"(r[2]), "=r"(r[3]) : "r"(a));
}
__device__ __forceinline__ void mma16816(float* c, const uint32_t* a,
                                         uint32_t b0, uint32_t b1) {
    asm volatile("mma.sync.aligned.m16n8k16.row.col.f32.bf16.bf16.f32 "
                 "{%0,%1,%2,%3},{%4,%5,%6,%7},{%8,%9},{%0,%1,%2,%3};"
                 : "+f"(c[0]), "+f"(c[1]), "+f"(c[2]), "+f"(c[3])
                 : "r"(a[0]), "r"(a[1]), "r"(a[2]), "r"(a[3]), "r"(b0), "r"(b1));
}
#define CP16(dst, src) \
    asm volatile("cp.async.cg.shared.global [%0],[%1],16;" :: "r"(dst), "l"(src))
#define CP_COMMIT() asm volatile("cp.async.commit_group;")
#define CP_WAIT0()  asm volatile("cp.async.wait_group 0;")
#define CP_WAIT1()  asm volatile("cp.async.wait_group 1;")

// fast exp on fma/alu pipes
__device__ __forceinline__ float fast_exp(float x) {
    x = fmaxf(x, -80.f);
    float t = x * 1.4426950408889634f;
    float r = t + 12582912.f;
    int   k = __float_as_int(r) - 0x4B400000;
    float f = t - (r - 12582912.f);
    float u = f * 0.6931471805599453f;
    float p = 8.3333333e-3f;
    p = fmaf(p, u, 4.1666667e-2f);
    p = fmaf(p, u, 1.6666667e-1f);
    p = fmaf(p, u, 5.0e-1f);
    p = fmaf(p, u, 1.0f);
    p = fmaf(p, u, 1.0f);
    return p * __int_as_float((k + 127) << 23);
}

// split x,y -> packed bf16 hi pair (return) + lo pair (*lo); low 16 bits = x
__device__ __forceinline__ uint32_t pack_hi_lo(float x, float y, uint32_t* lo) {
    __nv_bfloat16 hx = __float2bfloat16(x), hy = __float2bfloat16(y);
    __nv_bfloat16 lx = __float2bfloat16(x - __bfloat162float(hx));
    __nv_bfloat16 ly = __float2bfloat16(y - __bfloat162float(hy));
    *lo = ((uint32_t)__bfloat16_as_ushort(ly) << 16) | __bfloat16_as_ushort(lx);
    return ((uint32_t)__bfloat16_as_ushort(hy) << 16) | __bfloat16_as_ushort(hx);
}

__device__ __forceinline__ int rel_base(int t) {
    int d = t / 49, rem = t % 49;
    return d * 169 + (rem / 7) * 13 + (rem % 7);
}

// ===========================================================================
// fp32 -> bf16 hi/lo split; cols < nscale4 float4-groups of each row get *scale
// ===========================================================================
__global__ void convert_split(const float* __restrict__ s,
                              __nv_bfloat16* __restrict__ hi,
                              __nv_bfloat16* __restrict__ lo,
                              int n4, int width4, int nscale4, float scale)
{
    int i = blockIdx.x * blockDim.x + threadIdx.x;
    if (i >= n4) return;
    float4 v = ((const float4*)s)[i];
    float sc = ((i % width4) < nscale4) ? scale : 1.f;
    v.x *= sc; v.y *= sc; v.z *= sc; v.w *= sc;
    __nv_bfloat16 h0 = __float2bfloat16(v.x), h1 = __float2bfloat16(v.y);
    __nv_bfloat16 h2 = __float2bfloat16(v.z), h3 = __float2bfloat16(v.w);
    __nv_bfloat16 l0 = __float2bfloat16(v.x - __bfloat162float(h0));
    __nv_bfloat16 l1 = __float2bfloat16(v.y - __bfloat162float(h1));
    __nv_bfloat16 l2 = __float2bfloat16(v.z - __bfloat162float(h2));
    __nv_bfloat16 l3 = __float2bfloat16(v.w - __bfloat162float(h3));
    ((__nv_bfloat162*)hi)[2 * i]     = __nv_bfloat162(h0, h1);
    ((__nv_bfloat162*)hi)[2 * i + 1] = __nv_bfloat162(h2, h3);
    ((__nv_bfloat162*)lo)[2 * i]     = __nv_bfloat162(l0, l1);
    ((__nv_bfloat162*)lo)[2 * i + 1] = __nv_bfloat162(l2, l3);
}

// ===========================================================================
// bm[wi][h][n][m(pad 100)] = bias_table[relidx(n,m)][h] + mask[wi][n][m]
// ===========================================================================
__global__ void prep_bm(const float* __restrict__ mask,
                        const float* __restrict__ bias_table, int nW)
{
    int idx = blockIdx.x * blockDim.x + threadIdx.x;
    int total = nW * NHEAD * NTOK * 100;
    if (idx >= total) return;
    int m  = idx % 100;
    int n  = (idx / 100) % NTOK;
    int h  = (idx / (100 * NTOK)) % NHEAD;
    int wi = idx / (100 * NTOK * NHEAD);
    float v = 0.f;
    if (m < NTOK) {
        int ri = rel_base(n) - rel_base(m) + 253;
        v = __ldg(&bias_table[ri * NHEAD + h])
          + __ldg(&mask[((size_t)wi * NTOK + n) * NTOK + m]);
    }
    g_bm[idx] = v;
}

// ===========================================================================
// GEMM core: bf16x3, cp.async 3-stage.  BM=128 BN=256 BK=32, 512 threads,
// 16 warps (4M x 4N), warp tile 32x64.  Wide BN kills A re-read traffic.
// Chunk math (16B = 8 bf16):
//   A tile 128x32  -> 512 chunks  = 1 iter  @ 512 thr (4 chunks/row)
//   B tile  32x256 -> 1024 chunks = 2 iters @ 512 thr (32 chunks/row)
// ===========================================================================
#define BM 128
#define BN 256
#define BK 32
#define SA 40
#define SB 264
#define A_ELEMS (BM * SA)            // 5120
#define B_ELEMS (BK * SB)            // 8448
#define STAGE_ELEMS (2 * A_ELEMS + 2 * B_ELEMS)   // 27136 bf16 = 54272 B
#define NSTAGE 3
#define GTHR 512

static __device__ __forceinline__ void g2_load(
    const __nv_bfloat16* __restrict__ Ah, const __nv_bfloat16* __restrict__ Al,
    const __nv_bfloat16* __restrict__ Bh, const __nv_bfloat16* __restrict__ Bl,
    __nv_bfloat16* sm, int s, int M, int N, int m0, int n0, int kt, int tid)
{
    __nv_bfloat16* sAh = sm + (size_t)s * STAGE_ELEMS;
    __nv_bfloat16* sBh = sAh + 2 * A_ELEMS;
    // A: 512 chunks, 1 per thread
    {
        int idx = tid;
        int row = idx >> 2, ch = (idx & 3) << 3;
        int gr = m0 + row; if (gr >= M) gr = M - 1;
        size_t go = (size_t)gr * 256 + kt * BK + ch;
        uint32_t so = smem_u32(sAh + row * SA + ch);
        CP16(so, Ah + go);
        CP16(so + (uint32_t)(A_ELEMS * 2), Al + go);
    }
    // B: 1024 chunks, 2 per thread
    #pragma unroll
    for (int i = 0; i < 2; ++i) {
        int idx = tid + i * GTHR;
        int row = idx >> 5, ch = (idx & 31) << 3;
        size_t go = (size_t)(kt * BK + row) * N + n0 + ch;
        uint32_t so = smem_u32(sBh + row * SB + ch);
        CP16(so, Bh + go);
        CP16(so + (uint32_t)(B_ELEMS * 2), Bl + go);
    }
}

static __device__ __forceinline__ void g2_compute(const __nv_bfloat16* sm, int s,
                                                  int wr, int wc, int lane,
                                                  float acc[2][8][4])
{
    const __nv_bfloat16* sAh = sm + (size_t)s * STAGE_ELEMS;
    const __nv_bfloat16* sAl = sAh + A_ELEMS;
    const __nv_bfloat16* sBh = sAl + A_ELEMS;
    const __nv_bfloat16* sBl = sBh + B_ELEMS;
    const int sub = lane >> 3, w8 = lane & 7;
    #pragma unroll
    for (int ks = 0; ks < BK; ks += 16) {
        uint32_t ah[2][4], al[2][4], bh[4][4], bl[4][4];
        #pragma unroll
        for (int mf = 0; mf < 2; ++mf) {
            int row = wr + mf * 16 + w8 + (sub & 1) * 8;
            int col = ks + (sub >> 1) * 8;
            ldsm_x4(ah[mf], smem_u32(sAh + row * SA + col));
            ldsm_x4(al[mf], smem_u32(sAl + row * SA + col));
        }
        #pragma unroll
        for (int nf = 0; nf < 4; ++nf) {
            int krow = ks + w8 + (sub & 1) * 8;
            int col  = wc + nf * 16 + (sub >> 1) * 8;
            ldsm_x4t(bh[nf], smem_u32(sBh + krow * SB + col));
            ldsm_x4t(bl[nf], smem_u32(sBl + krow * SB + col));
        }
        #pragma unroll
        for (int mf = 0; mf < 2; ++mf)
            #pragma unroll
            for (int nf = 0; nf < 8; ++nf) {
                uint32_t b0h = bh[nf >> 1][(nf & 1) * 2];
                uint32_t b1h = bh[nf >> 1][(nf & 1) * 2 + 1];
                uint32_t b0l = bl[nf >> 1][(nf & 1) * 2];
                uint32_t b1l = bl[nf >> 1][(nf & 1) * 2 + 1];
                mma16816(acc[mf][nf], ah[mf], b0h, b1h);
                mma16816(acc[mf][nf], ah[mf], b0l, b1l);
                mma16816(acc[mf][nf], al[mf], b0h, b1h);
            }
    }
}

// 3-stage mainloop, single barrier per iteration.
#define G2_MAINLOOP()                                                        \
    float acc[2][8][4];                                                      \
    _Pragma("unroll")                                                        \
    for (int i = 0; i < 2; ++i)                                              \
        _Pragma("unroll")                                                    \
        for (int j = 0; j < 8; ++j)                                          \
            _Pragma("unroll")                                                \
            for (int k = 0; k < 4; ++k) acc[i][j][k] = 0.f;                  \
    const int NT = 256 / BK;                                                 \
    g2_load(Ah, Al, Bh, Bl, sm, 0, M, N, m0, n0, 0, tid);                    \
    CP_COMMIT();                                                             \
    g2_load(Ah, Al, Bh, Bl, sm, 1, M, N, m0, n0, 1, tid);                    \
    CP_COMMIT();                                                             \
    _Pragma("unroll 1")                                                      \
    for (int kt = 0; kt < NT; ++kt) {                                        \
        if (kt + 1 < NT) { CP_WAIT1(); } else { CP_WAIT0(); }                \
        __syncthreads();                                                     \
        g2_compute(sm, kt % NSTAGE, wr, wc, lane, acc);                      \
        if (kt + 2 < NT) {                                                   \
            g2_load(Ah, Al, Bh, Bl, sm, (kt + 2) % NSTAGE, M, N, m0, n0,     \
                    kt + 2, tid);                                            \
            CP_COMMIT();                                                     \
        }                                                                    \
    }

// fp32 output + bias (proj path)
__global__ void __launch_bounds__(GTHR, 1)
gemm2(const __nv_bfloat16* __restrict__ Ah, const __nv_bfloat16* __restrict__ Al,
      const __nv_bfloat16* __restrict__ Bh, const __nv_bfloat16* __restrict__ Bl,
      const float* __restrict__ bias, float* __restrict__ C, int M, int N)
{
    __nv_bfloat16* sm = (__nv_bfloat16*)smem_raw;
    const int tid  = threadIdx.x;
    const int warp = tid >> 5, lane = tid & 31;
    const int m0 = blockIdx.x * BM;
    const int n0 = blockIdx.y * BN;
    const int wr = (warp & 3) * 32;
    const int wc = (warp >> 2) * 64;

    G2_MAINLOOP();

    const int r4 = lane >> 2, c2 = (lane & 3) * 2;
    #pragma unroll
    for (int mf = 0; mf < 2; ++mf)
        #pragma unroll
        for (int nf = 0; nf < 8; ++nf) {
            int col = n0 + wc + nf * 8 + c2;
            float b0 = __ldg(bias + col);
            float b1 = __ldg(bias + col + 1);
            int row = m0 + wr + mf * 16 + r4;
            if (row < M) {
                float2 v = make_float2(acc[mf][nf][0] + b0, acc[mf][nf][1] + b1);
                *(float2*)(C + (size_t)row * N + col) = v;
            }
            if (row + 8 < M) {
                float2 v = make_float2(acc[mf][nf][2] + b0, acc[mf][nf][3] + b1);
                *(float2*)(C + (size_t)(row + 8) * N + col) = v;
            }
        }
}

// bf16 hi/lo split output, no bias (qkv path)
__global__ void __launch_bounds__(GTHR, 1)
gemm2b(const __nv_bfloat16* __restrict__ Ah, const __nv_bfloat16* __restrict__ Al,
       const __nv_bfloat16* __restrict__ Bh, const __nv_bfloat16* __restrict__ Bl,
       __nv_bfloat16* __restrict__ Ch, __nv_bfloat16* __restrict__ Cl,
       int M, int N)
{
    __nv_bfloat16* sm = (__nv_bfloat16*)smem_raw;
    const int tid  = threadIdx.x;
    const int warp = tid >> 5, lane = tid & 31;
    const int m0 = blockIdx.x * BM;
    const int n0 = blockIdx.y * BN;
    const int wr = (warp & 3) * 32;
    const int wc = (warp >> 2) * 64;

    G2_MAINLOOP();

    const int r4 = lane >> 2, c2 = (lane & 3) * 2;
    #pragma unroll
    for (int mf = 0; mf < 2; ++mf)
        #pragma unroll
        for (int nf = 0; nf < 8; ++nf) {
            int col = n0 + wc + nf * 8 + c2;
            int row = m0 + wr + mf * 16 + r4;
            if (row < M) {
                uint32_t lo, hi = pack_hi_lo(acc[mf][nf][0], acc[mf][nf][1], &lo);
                *(uint32_t*)(Ch + (size_t)row * N + col) = hi;
                *(uint32_t*)(Cl + (size_t)row * N + col) = lo;
            }
            if (row + 8 < M) {
                uint32_t lo, hi = pack_hi_lo(acc[mf][nf][2], acc[mf][nf][3], &lo);
                *(uint32_t*)(Ch + (size_t)(row + 8) * N + col) = hi;
                *(uint32_t*)(Cl + (size_t)(row + 8) * N + col) = lo;
            }
        }
}

// ===========================================================================
// attn4: one CTA (128 thr) per (window, head). cp.async q/k/v prologue,
// mma core, bm read straight from L2.
// smem: q[128x40]h/l k[112x40]h/l v[112x40]h/l  bf16 = 56320 B
// ===========================================================================
__global__ void __launch_bounds__(128, 2)
attn4(const __nv_bfloat16* __restrict__ Qh, const __nv_bfloat16* __restrict__ Ql,
      int nW)
{
    __nv_bfloat16* qh = (__nv_bfloat16*)smem_raw;   // 128x40
    __nv_bfloat16* ql = qh + 5120;
    __nv_bfloat16* kh = ql + 5120;                  // 112x40
    __nv_bfloat16* kl = kh + 4480;
    __nv_bfloat16* vh = kl + 4480;
    __nv_bfloat16* vl = vh + 4480;

    const int b    = blockIdx.x >> 3;
    const int h    = blockIdx.x & 7;
    const int tid  = threadIdx.x;
    const int lane = tid & 31;
    const int warp = tid >> 5;
    const int wi   = b % nW;

    // zero V padding rows 98..111 (hi+lo)
    {
        uint32_t* zv = (uint32_t*)(vh + 98 * 40);
        uint32_t* zl = (uint32_t*)(vl + 98 * 40);
        for (int i = tid; i < 280; i += 128) { zv[i] = 0; zl[i] = 0; }
    }

    // cp.async: q/k/v hi+lo slabs (32 cols of head h)
    {
        __nv_bfloat16* mats[6] = {qh, ql, kh, kl, vh, vl};
        for (int idx = tid; idx < 2352; idx += 128) {
            int chunk = idx & 3;
            int row   = (idx >> 2) % 98;
            int mat   = idx / 392;
            int grp   = mat >> 1;
            const __nv_bfloat16* src = (mat & 1) ? Ql : Qh;
            size_t go = ((size_t)b * NTOK + row) * 768 + grp * 256 + h * 32 + chunk * 8;
            CP16(smem_u32(mats[mat] + row * 40 + chunk * 8), src + go);
        }
    }
    CP_COMMIT();
    CP_WAIT0();
    __syncthreads();

    const int wr  = warp * 32;
    const int sub = lane >> 3, w8 = lane & 7;
    const int r4  = lane >> 2, c2 = (lane & 3) * 2;

    // ---- S = q k^T (scale pre-folded into Wq), bf16x3 ----------------------
    float S[2][14][4];
    #pragma unroll
    for (int mt = 0; mt < 2; ++mt)
        #pragma unroll
        for (int nt = 0; nt < 14; ++nt)
            #pragma unroll
            for (int i = 0; i < 4; ++i) S[mt][nt][i] = 0.f;

    #pragma unroll
    for (int ks = 0; ks < 2; ++ks) {
        uint32_t aqh[2][4], aql[2][4];
        #pragma unroll
        for (int mt = 0; mt < 2; ++mt) {
            int row = wr + mt * 16 + w8 + (sub & 1) * 8;
            int col = ks * 16 + (sub >> 1) * 8;
            ldsm_x4(aqh[mt], smem_u32(qh + row * 40 + col));
            ldsm_x4(aql[mt], smem_u32(ql + row * 40 + col));
        }
        #pragma unroll
        for (int nt2 = 0; nt2 < 7; ++nt2) {
            uint32_t bkh[4], bkl[4];
            int row = nt2 * 16 + w8 + (sub & 1) * 8;
            int col = ks * 16 + (sub >> 1) * 8;
            ldsm_x4(bkh, smem_u32(kh + row * 40 + col));
            ldsm_x4(bkl, smem_u32(kl + row * 40 + col));
            #pragma unroll
            for (int mt = 0; mt < 2; ++mt) {
                mma16816(S[mt][nt2 * 2],     aqh[mt], bkh[0], bkh[2]);
                mma16816(S[mt][nt2 * 2],     aqh[mt], bkl[0], bkl[2]);
                mma16816(S[mt][nt2 * 2],     aql[mt], bkh[0], bkh[2]);
                mma16816(S[mt][nt2 * 2 + 1], aqh[mt], bkh[1], bkh[3]);
                mma16816(S[mt][nt2 * 2 + 1], aqh[mt], bkl[1], bkl[3]);
                mma16816(S[mt][nt2 * 2 + 1], aql[mt], bkh[1], bkh[3]);
            }
        }
    }

    // ---- + (bias+mask) direct from L2, -1e9 padding ------------------------
    const float* slab = g_bm + (size_t)(wi * NHEAD + h) * (NTOK * 100);
    #pragma unroll
    for (int mt = 0; mt < 2; ++mt) {
        #pragma unroll
        for (int half = 0; half < 2; ++half) {
            int row = wr + mt * 16 + r4 + half * 8;
            bool rv = row < NTOK;
            const float* bmrow = slab + (rv ? row : 0) * 100;
            #pragma unroll
            for (int nt = 0; nt < 14; ++nt) {
                int col = nt * 8 + c2;
                float* sp = &S[mt][nt][half * 2];
                if (rv && col < NTOK) {
                    float2 bm2 = __ldg((const float2*)(bmrow + col));
                    sp[0] += bm2.x;
                    sp[1] += bm2.y;
                } else {
                    sp[0] = -1e9f;
                    sp[1] = -1e9f;
                }
            }
        }
    }

    // ---- softmax in registers (deferred normalization) ---------------------
    float inv_[2][2];
    #pragma unroll
    for (int mt = 0; mt < 2; ++mt)
        #pragma unroll
        for (int half = 0; half < 2; ++half) {
            float mx = -1e30f;
            #pragma unroll
            for (int nt = 0; nt < 14; ++nt)
                mx = fmaxf(mx, fmaxf(S[mt][nt][half * 2], S[mt][nt][half * 2 + 1]));
            mx = fmaxf(mx, __shfl_xor_sync(0xffffffffu, mx, 1));
            mx = fmaxf(mx, __shfl_xor_sync(0xffffffffu, mx, 2));
            float sum = 0.f;
            #pragma unroll
            for (int nt = 0; nt < 14; ++nt) {
                float e0 = fast_exp(S[mt][nt][half * 2]     - mx);
                float e1 = fast_exp(S[mt][nt][half * 2 + 1] - mx);
                S[mt][nt][half * 2]     = e0;
                S[mt][nt][half * 2 + 1] = e1;
                sum += e0 + e1;
            }
            sum += __shfl_xor_sync(0xffffffffu, sum, 1);
            sum += __shfl_xor_sync(0xffffffffu, sum, 2);
            inv_[mt][half] = __fdividef(1.f, sum);
        }

    // ---- O = P @ V (bf16x3) ------------------------------------------------
    float O[2][4][4];
    #pragma unroll
    for (int mt = 0; mt < 2; ++mt)
        #pragma unroll
        for (int nf = 0; nf < 4; ++nf)
            #pragma unroll
            for (int i = 0; i < 4; ++i) O[mt][nf][i] = 0.f;

    #pragma unroll
    for (int kt = 0; kt < 7; ++kt) {
        uint32_t vfh[2][4], vfl[2][4];
        #pragma unroll
        for (int j = 0; j < 2; ++j) {
            int row = kt * 16 + w8 + (sub & 1) * 8;
            int col = j * 16 + (sub >> 1) * 8;
            ldsm_x4t(vfh[j], smem_u32(vh + row * 40 + col));
            ldsm_x4t(vfl[j], smem_u32(vl + row * 40 + col));
        }
        #pragma unroll
        for (int mt = 0; mt < 2; ++mt) {
            const float* cA = S[mt][2 * kt];
            const float* cB = S[mt][2 * kt + 1];
            uint32_t Ph[4], Pl[4];
            Ph[0] = pack_hi_lo(cA[0], cA[1], &Pl[0]);
            Ph[1] = pack_hi_lo(cA[2], cA[3], &Pl[1]);
            Ph[2] = pack_hi_lo(cB[0], cB[1], &Pl[2]);
            Ph[3] = pack_hi_lo(cB[2], cB[3], &Pl[3]);
            #pragma unroll
            for (int nf = 0; nf < 4; ++nf) {
                uint32_t b0h = vfh[nf >> 1][(nf & 1) * 2];
                uint32_t b1h = vfh[nf >> 1][(nf & 1) * 2 + 1];
                uint32_t b0l = vfl[nf >> 1][(nf & 1) * 2];
                uint32_t b1l = vfl[nf >> 1][(nf & 1) * 2 + 1];
                mma16816(O[mt][nf], Ph, b0h, b1h);
                mma16816(O[mt][nf], Ph, b0l, b1l);
                mma16816(O[mt][nf], Pl, b0h, b1h);
            }
        }
    }

    // ---- store normalized, hi/lo split, vectorized -------------------------
    #pragma unroll
    for (int mt = 0; mt < 2; ++mt)
        #pragma unroll
        for (int half = 0; half < 2; ++half) {
            int row = wr + mt * 16 + r4 + half * 8;
            if (row < NTOK) {
                float s = inv_[mt][half];
                #pragma unroll
                for (int nf = 0; nf < 4; ++nf) {
                    float v0 = O[mt][nf][half * 2]     * s;
                    float v1 = O[mt][nf][half * 2 + 1] * s;
                    int col = h * 32 + nf * 8 + c2;
                    size_t off = ((size_t)b * NTOK + row) * CDIM + col;
                    uint32_t lo, hi = pack_hi_lo(v0, v1, &lo);
                    *(uint32_t*)(g_ah + off) = hi;
                    *(uint32_t*)(g_al + off) = lo;
                }
            }
        }
}

// ===========================================================================
extern "C" void kernel_launch(void* const* d_in, const int* in_sizes, int n_in,
                              void* d_out, int out_size)
{
    const float* x          = (const float*)d_in[0];
    const float* mask       = (const float*)d_in[1];
    const float* qkv_w      = (const float*)d_in[2];
    const float* proj_w     = (const float*)d_in[3];
    const float* proj_b     = (const float*)d_in[4];
    const float* bias_table = (const float*)d_in[5];

    int B  = in_sizes[0] / (NTOK * CDIM);
    int nW = in_sizes[1] / (NTOK * NTOK);
    if (B > MAXB) B = MAXB;
    if (nW > MAXNW) nW = MAXNW;
    const int M = B * NTOK;
    const float scale = 0.17677669529663689f;   // 32^-0.5

    const size_t smem_g = (size_t)STAGE_ELEMS * NSTAGE * sizeof(__nv_bfloat16); // 162816
    const size_t smem_a = 56320;

    cudaFuncSetAttribute(gemm2,  cudaFuncAttributeMaxDynamicSharedMemorySize, (int)smem_g);
    cudaFuncSetAttribute(gemm2b, cudaFuncAttributeMaxDynamicSharedMemorySize, (int)smem_g);
    cudaFuncSetAttribute(attn4,  cudaFuncAttributeMaxDynamicSharedMemorySize, (int)smem_a);

    void* xh_p   = nullptr; cudaGetSymbolAddress(&xh_p,   g_xh);
    void* xl_p   = nullptr; cudaGetSymbolAddress(&xl_p,   g_xl);
    void* qkvh_p = nullptr; cudaGetSymbolAddress(&qkvh_p, g_qkvh);
    void* qkvl_p = nullptr; cudaGetSymbolAddress(&qkvl_p, g_qkvl);
    void* ah_p   = nullptr; cudaGetSymbolAddress(&ah_p,   g_ah);
    void* al_p   = nullptr; cudaGetSymbolAddress(&al_p,   g_al);
    void* wqh_p  = nullptr; cudaGetSymbolAddress(&wqh_p,  g_wqh);
    void* wql_p  = nullptr; cudaGetSymbolAddress(&wql_p,  g_wql);
    void* wph_p  = nullptr; cudaGetSymbolAddress(&wph_p,  g_wph);
    void* wpl_p  = nullptr; cudaGetSymbolAddress(&wpl_p,  g_wpl);

    // input/weight splits (q-scale folded into Wq columns 0..255)
    {
        int n4 = M * CDIM / 4;
        convert_split<<<(n4 + 255) / 256, 256>>>(x, (__nv_bfloat16*)xh_p,
                                                 (__nv_bfloat16*)xl_p, n4, 64, 0, 1.f);
        int w1 = CDIM * 3 * CDIM / 4;
        convert_split<<<(w1 + 255) / 256, 256>>>(qkv_w, (__nv_bfloat16*)wqh_p,
                                                 (__nv_bfloat16*)wql_p, w1, 192, 64, scale);
        int w2 = CDIM * CDIM / 4;
        convert_split<<<(w2 + 255) / 256, 256>>>(proj_w, (__nv_bfloat16*)wph_p,
                                                 (__nv_bfloat16*)wpl_p, w2, 64, 0, 1.f);
        int nbm = nW * NHEAD * NTOK * 100;
        prep_bm<<<(nbm + 255) / 256, 256>>>(mask, bias_table, nW);
    }

    dim3 g1((M + BM - 1) / BM, (3 * CDIM) / BN);   // 1568 x 3
    gemm2b<<<g1, GTHR, smem_g>>>((__nv_bfloat16*)xh_p, (__nv_bfloat16*)xl_p,
                                 (__nv_bfloat16*)wqh_p, (__nv_bfloat16*)wql_p,
                                 (__nv_bfloat16*)qkvh_p, (__nv_bfloat16*)qkvl_p,
                                 M, 3 * CDIM);

    attn4<<<B * NHEAD, 128, smem_a>>>((__nv_bfloat16*)qkvh_p,
                                      (__nv_bfloat16*)qkvl_p, nW);

    dim3 g2d((M + BM - 1) / BM, CDIM / BN);        // 1568 x 1
    gemm2<<<g2d, GTHR, smem_g>>>((__nv_bfloat16*)ah_p, (__nv_bfloat16*)al_p,
                                 (__nv_bfloat16*)wph_p, (__nv_bfloat16*)wpl_p,
                                 proj_b, (float*)d_out, M, CDIM);
}

// round 16
// speedup vs baseline: 1.1338x; 1.1338x over previous
#include <cuda_runtime.h>
#include <cuda_bf16.h>
#include <math.h>
#include <stdint.h>

#define NTOK 98
#define CDIM 256
#define NHEAD 8
#define DH 32
#define MAXB 2048
#define MAXM (MAXB * NTOK)
#define MAXNW 64

// scratch (no allocs allowed -> device globals)
__device__ __nv_bfloat16 g_xh[(size_t)MAXM * CDIM];
__device__ __nv_bfloat16 g_xl[(size_t)MAXM * CDIM];
__device__ __nv_bfloat16 g_qkvh[(size_t)MAXM * 3 * CDIM];   // qkv hi [B*N,768]
__device__ __nv_bfloat16 g_qkvl[(size_t)MAXM * 3 * CDIM];   // qkv lo
__device__ __nv_bfloat16 g_ah[(size_t)MAXM * CDIM];         // attn out hi
__device__ __nv_bfloat16 g_al[(size_t)MAXM * CDIM];         // attn out lo
__device__ __nv_bfloat16 g_wqh[CDIM * 3 * CDIM];
__device__ __nv_bfloat16 g_wql[CDIM * 3 * CDIM];
__device__ __nv_bfloat16 g_wph[CDIM * CDIM];
__device__ __nv_bfloat16 g_wpl[CDIM * CDIM];
__device__ float g_bm[(size_t)MAXNW * NHEAD * NTOK * 100];  // bias+mask slabs

extern __shared__ unsigned char smem_raw[];

// ===========================================================================
// helpers
// ===========================================================================
__device__ __forceinline__ uint32_t smem_u32(const void* p) {
    return (uint32_t)__cvta_generic_to_shared(p);
}
__device__ __forceinline__ void ldsm_x4(uint32_t* r, uint32_t a) {
    asm volatile("ldmatrix.sync.aligned.m8n8.x4.shared.b16 {%0,%1,%2,%3},[%4];"
                 : "=r"(r[0]), "=r"(r[1]), "=r"(r[2]), "=r"(r[3]) : "r"(a));
}
__device__ __forceinline__ void ldsm_x4t(uint32_t* r, uint32_t a) {
    asm volatile("ldmatrix.sync.aligned.m8n8.x4.trans.shared.b16 {%0,%1,%2,%3},[%4];"
                 : "=r"(r[0]), "=r"(r[1]), "=r"(r[2]), "=r"(r[3]) : "r"(a));
}
__device__ __forceinline__ void mma16816(float* c, const uint32_t* a,
                                         uint32_t b0, uint32_t b1) {
    asm volatile("mma.sync.aligned.m16n8k16.row.col.f32.bf16.bf16.f32 "
                 "{%0,%1,%2,%3},{%4,%5,%6,%7},{%8,%9},{%0,%1,%2,%3};"
                 : "+f"(c[0]), "+f"(c[1]), "+f"(c[2]), "+f"(c[3])
                 : "r"(a[0]), "r"(a[1]), "r"(a[2]), "r"(a[3]), "r"(b0), "r"(b1));
}
#define CP16(dst, src) \
    asm volatile("cp.async.cg.shared.global [%0],[%1],16;" :: "r"(dst), "l"(src))
#define CP_COMMIT() asm volatile("cp.async.commit_group;")
#define CP_WAIT0()  asm volatile("cp.async.wait_group 0;")
#define CP_WAIT1()  asm volatile("cp.async.wait_group 1;")

// fast exp on fma/alu pipes
__device__ __forceinline__ float fast_exp(float x) {
    x = fmaxf(x, -80.f);
    float t = x * 1.4426950408889634f;
    float r = t + 12582912.f;
    int   k = __float_as_int(r) - 0x4B400000;
    float f = t - (r - 12582912.f);
    float u = f * 0.6931471805599453f;
    float p = 8.3333333e-3f;
    p = fmaf(p, u, 4.1666667e-2f);
    p = fmaf(p, u, 1.6666667e-1f);
    p = fmaf(p, u, 5.0e-1f);
    p = fmaf(p, u, 1.0f);
    p = fmaf(p, u, 1.0f);
    return p * __int_as_float((k + 127) << 23);
}

// split x,y -> packed bf16 hi pair (return) + lo pair (*lo); low 16 bits = x
__device__ __forceinline__ uint32_t pack_hi_lo(float x, float y, uint32_t* lo) {
    __nv_bfloat16 hx = __float2bfloat16(x), hy = __float2bfloat16(y);
    __nv_bfloat16 lx = __float2bfloat16(x - __bfloat162float(hx));
    __nv_bfloat16 ly = __float2bfloat16(y - __bfloat162float(hy));
    *lo = ((uint32_t)__bfloat16_as_ushort(ly) << 16) | __bfloat16_as_ushort(lx);
    return ((uint32_t)__bfloat16_as_ushort(hy) << 16) | __bfloat16_as_ushort(hx);
}

__device__ __forceinline__ int rel_base(int t) {
    int d = t / 49, rem = t % 49;
    return d * 169 + (rem / 7) * 13 + (rem % 7);
}

// ===========================================================================
// fp32 -> bf16 hi/lo split; cols < nscale4 float4-groups of each row get *scale
// ===========================================================================
__global__ void convert_split(const float* __restrict__ s,
                              __nv_bfloat16* __restrict__ hi,
                              __nv_bfloat16* __restrict__ lo,
                              int n4, int width4, int nscale4, float scale)
{
    int i = blockIdx.x * blockDim.x + threadIdx.x;
    if (i >= n4) return;
    float4 v = ((const float4*)s)[i];
    float sc = ((i % width4) < nscale4) ? scale : 1.f;
    v.x *= sc; v.y *= sc; v.z *= sc; v.w *= sc;
    __nv_bfloat16 h0 = __float2bfloat16(v.x), h1 = __float2bfloat16(v.y);
    __nv_bfloat16 h2 = __float2bfloat16(v.z), h3 = __float2bfloat16(v.w);
    __nv_bfloat16 l0 = __float2bfloat16(v.x - __bfloat162float(h0));
    __nv_bfloat16 l1 = __float2bfloat16(v.y - __bfloat162float(h1));
    __nv_bfloat16 l2 = __float2bfloat16(v.z - __bfloat162float(h2));
    __nv_bfloat16 l3 = __float2bfloat16(v.w - __bfloat162float(h3));
    ((__nv_bfloat162*)hi)[2 * i]     = __nv_bfloat162(h0, h1);
    ((__nv_bfloat162*)hi)[2 * i + 1] = __nv_bfloat162(h2, h3);
    ((__nv_bfloat162*)lo)[2 * i]     = __nv_bfloat162(l0, l1);
    ((__nv_bfloat162*)lo)[2 * i + 1] = __nv_bfloat162(l2, l3);
}

// ===========================================================================
// bm[wi][h][n][m(pad 100)] = bias_table[relidx(n,m)][h] + mask[wi][n][m]
// ===========================================================================
__global__ void prep_bm(const float* __restrict__ mask,
                        const float* __restrict__ bias_table, int nW)
{
    int idx = blockIdx.x * blockDim.x + threadIdx.x;
    int total = nW * NHEAD * NTOK * 100;
    if (idx >= total) return;
    int m  = idx % 100;
    int n  = (idx / 100) % NTOK;
    int h  = (idx / (100 * NTOK)) % NHEAD;
    int wi = idx / (100 * NTOK * NHEAD);
    float v = 0.f;
    if (m < NTOK) {
        int ri = rel_base(n) - rel_base(m) + 253;
        v = __ldg(&bias_table[ri * NHEAD + h])
          + __ldg(&mask[((size_t)wi * NTOK + n) * NTOK + m]);
    }
    g_bm[idx] = v;
}

// ===========================================================================
// GEMM core: bf16x3, cp.async 3-stage (R13 config: BM=128 BN=128 BK=32,
// 256 threads, 2 CTAs/SM — measured best).
// ===========================================================================
#define BM 128
#define BN 128
#define BK 32
#define SA 40
#define SB 136
#define A_ELEMS (BM * SA)
#define B_ELEMS (BK * SB)
#define STAGE_ELEMS (2 * A_ELEMS + 2 * B_ELEMS)
#define NSTAGE 3

static __device__ __forceinline__ void g2_load(
    const __nv_bfloat16* __restrict__ Ah, const __nv_bfloat16* __restrict__ Al,
    const __nv_bfloat16* __restrict__ Bh, const __nv_bfloat16* __restrict__ Bl,
    __nv_bfloat16* sm, int s, int M, int N, int m0, int n0, int kt, int tid)
{
    __nv_bfloat16* sAh = sm + (size_t)s * STAGE_ELEMS;
    __nv_bfloat16* sBh = sAh + 2 * A_ELEMS;
    #pragma unroll
    for (int i = 0; i < 2; ++i) {
        int idx = tid + i * 256;
        int row = idx >> 2, ch = (idx & 3) << 3;
        int gr = m0 + row; if (gr >= M) gr = M - 1;
        size_t go = (size_t)gr * 256 + kt * BK + ch;
        uint32_t so = smem_u32(sAh + row * SA + ch);
        CP16(so, Ah + go);
        CP16(so + (uint32_t)(A_ELEMS * 2), Al + go);
    }
    #pragma unroll
    for (int i = 0; i < 2; ++i) {
        int idx = tid + i * 256;
        int row = idx >> 4, ch = (idx & 15) << 3;
        size_t go = (size_t)(kt * BK + row) * N + n0 + ch;
        uint32_t so = smem_u32(sBh + row * SB + ch);
        CP16(so, Bh + go);
        CP16(so + (uint32_t)(B_ELEMS * 2), Bl + go);
    }
}

static __device__ __forceinline__ void g2_compute(const __nv_bfloat16* sm, int s,
                                                  int wr, int wc, int lane,
                                                  float acc[2][8][4])
{
    const __nv_bfloat16* sAh = sm + (size_t)s * STAGE_ELEMS;
    const __nv_bfloat16* sAl = sAh + A_ELEMS;
    const __nv_bfloat16* sBh = sAl + A_ELEMS;
    const __nv_bfloat16* sBl = sBh + B_ELEMS;
    const int sub = lane >> 3, w8 = lane & 7;
    #pragma unroll
    for (int ks = 0; ks < BK; ks += 16) {
        uint32_t ah[2][4], al[2][4], bh[4][4], bl[4][4];
        #pragma unroll
        for (int mf = 0; mf < 2; ++mf) {
            int row = wr + mf * 16 + w8 + (sub & 1) * 8;
            int col = ks + (sub >> 1) * 8;
            ldsm_x4(ah[mf], smem_u32(sAh + row * SA + col));
            ldsm_x4(al[mf], smem_u32(sAl + row * SA + col));
        }
        #pragma unroll
        for (int nf = 0; nf < 4; ++nf) {
            int krow = ks + w8 + (sub & 1) * 8;
            int col  = wc + nf * 16 + (sub >> 1) * 8;
            ldsm_x4t(bh[nf], smem_u32(sBh + krow * SB + col));
            ldsm_x4t(bl[nf], smem_u32(sBl + krow * SB + col));
        }
        #pragma unroll
        for (int mf = 0; mf < 2; ++mf)
            #pragma unroll
            for (int nf = 0; nf < 8; ++nf) {
                uint32_t b0h = bh[nf >> 1][(nf & 1) * 2];
                uint32_t b1h = bh[nf >> 1][(nf & 1) * 2 + 1];
                uint32_t b0l = bl[nf >> 1][(nf & 1) * 2];
                uint32_t b1l = bl[nf >> 1][(nf & 1) * 2 + 1];
                mma16816(acc[mf][nf], ah[mf], b0h, b1h);
                mma16816(acc[mf][nf], ah[mf], b0l, b1l);
                mma16816(acc[mf][nf], al[mf], b0h, b1h);
            }
    }
}

// 3-stage mainloop, single barrier per iteration.
#define G2_MAINLOOP()                                                        \
    float acc[2][8][4];                                                      \
    _Pragma("unroll")                                                        \
    for (int i = 0; i < 2; ++i)                                              \
        _Pragma("unroll")                                                    \
        for (int j = 0; j < 8; ++j)                                          \
            _Pragma("unroll")                                                \
            for (int k = 0; k < 4; ++k) acc[i][j][k] = 0.f;                  \
    const int NT = 256 / BK;                                                 \
    g2_load(Ah, Al, Bh, Bl, sm, 0, M, N, m0, n0, 0, tid);                    \
    CP_COMMIT();                                                             \
    g2_load(Ah, Al, Bh, Bl, sm, 1, M, N, m0, n0, 1, tid);                    \
    CP_COMMIT();                                                             \
    _Pragma("unroll 1")                                                      \
    for (int kt = 0; kt < NT; ++kt) {                                        \
        if (kt + 1 < NT) { CP_WAIT1(); } else { CP_WAIT0(); }                \
        __syncthreads();                                                     \
        g2_compute(sm, kt % NSTAGE, wr, wc, lane, acc);                      \
        if (kt + 2 < NT) {                                                   \
            g2_load(Ah, Al, Bh, Bl, sm, (kt + 2) % NSTAGE, M, N, m0, n0,     \
                    kt + 2, tid);                                            \
            CP_COMMIT();                                                     \
        }                                                                    \
    }

// fp32 output + bias (proj path)
__global__ void __launch_bounds__(256, 2)
gemm2(const __nv_bfloat16* __restrict__ Ah, const __nv_bfloat16* __restrict__ Al,
      const __nv_bfloat16* __restrict__ Bh, const __nv_bfloat16* __restrict__ Bl,
      const float* __restrict__ bias, float* __restrict__ C, int M, int N)
{
    __nv_bfloat16* sm = (__nv_bfloat16*)smem_raw;
    const int tid  = threadIdx.x;
    const int warp = tid >> 5, lane = tid & 31;
    const int m0 = blockIdx.x * BM;
    const int n0 = blockIdx.y * BN;
    const int wr = (warp & 3) * 32;
    const int wc = (warp >> 2) * 64;

    G2_MAINLOOP();

    const int r4 = lane >> 2, c2 = (lane & 3) * 2;
    #pragma unroll
    for (int mf = 0; mf < 2; ++mf)
        #pragma unroll
        for (int nf = 0; nf < 8; ++nf) {
            int col = n0 + wc + nf * 8 + c2;
            float b0 = __ldg(bias + col);
            float b1 = __ldg(bias + col + 1);
            int row = m0 + wr + mf * 16 + r4;
            if (row < M) {
                float2 v = make_float2(acc[mf][nf][0] + b0, acc[mf][nf][1] + b1);
                *(float2*)(C + (size_t)row * N + col) = v;
            }
            if (row + 8 < M) {
                float2 v = make_float2(acc[mf][nf][2] + b0, acc[mf][nf][3] + b1);
                *(float2*)(C + (size_t)(row + 8) * N + col) = v;
            }
        }
}

// bf16 hi/lo split output, no bias (qkv path)
__global__ void __launch_bounds__(256, 2)
gemm2b(const __nv_bfloat16* __restrict__ Ah, const __nv_bfloat16* __restrict__ Al,
       const __nv_bfloat16* __restrict__ Bh, const __nv_bfloat16* __restrict__ Bl,
       __nv_bfloat16* __restrict__ Ch, __nv_bfloat16* __restrict__ Cl,
       int M, int N)
{
    __nv_bfloat16* sm = (__nv_bfloat16*)smem_raw;
    const int tid  = threadIdx.x;
    const int warp = tid >> 5, lane = tid & 31;
    const int m0 = blockIdx.x * BM;
    const int n0 = blockIdx.y * BN;
    const int wr = (warp & 3) * 32;
    const int wc = (warp >> 2) * 64;

    G2_MAINLOOP();

    const int r4 = lane >> 2, c2 = (lane & 3) * 2;
    #pragma unroll
    for (int mf = 0; mf < 2; ++mf)
        #pragma unroll
        for (int nf = 0; nf < 8; ++nf) {
            int col = n0 + wc + nf * 8 + c2;
            int row = m0 + wr + mf * 16 + r4;
            if (row < M) {
                uint32_t lo, hi = pack_hi_lo(acc[mf][nf][0], acc[mf][nf][1], &lo);
                *(uint32_t*)(Ch + (size_t)row * N + col) = hi;
                *(uint32_t*)(Cl + (size_t)row * N + col) = lo;
            }
            if (row + 8 < M) {
                uint32_t lo, hi = pack_hi_lo(acc[mf][nf][2], acc[mf][nf][3], &lo);
                *(uint32_t*)(Ch + (size_t)(row + 8) * N + col) = hi;
                *(uint32_t*)(Cl + (size_t)(row + 8) * N + col) = lo;
            }
        }
}

// ===========================================================================
// attn5: one CTA (256 thr, 8 warps) per (window, head).  16 rows per warp
// -> half the register pressure of attn4, 2x the warps per SM.
// smem: q[128x40]h/l k[112x40]h/l v[112x40]h/l  bf16 = 56320 B
// ===========================================================================
__global__ void __launch_bounds__(256, 2)
attn5(const __nv_bfloat16* __restrict__ Qh, const __nv_bfloat16* __restrict__ Ql,
      int nW)
{
    __nv_bfloat16* qh = (__nv_bfloat16*)smem_raw;   // 128x40
    __nv_bfloat16* ql = qh + 5120;
    __nv_bfloat16* kh = ql + 5120;                  // 112x40
    __nv_bfloat16* kl = kh + 4480;
    __nv_bfloat16* vh = kl + 4480;
    __nv_bfloat16* vl = vh + 4480;

    const int b    = blockIdx.x >> 3;
    const int h    = blockIdx.x & 7;
    const int tid  = threadIdx.x;
    const int lane = tid & 31;
    const int warp = tid >> 5;
    const int wi   = b % nW;

    // zero V padding rows 98..111 (hi+lo)
    {
        uint32_t* zv = (uint32_t*)(vh + 98 * 40);
        uint32_t* zl = (uint32_t*)(vl + 98 * 40);
        for (int i = tid; i < 280; i += 256) { zv[i] = 0; zl[i] = 0; }
    }

    // cp.async: q/k/v hi+lo slabs (32 cols of head h)
    {
        __nv_bfloat16* mats[6] = {qh, ql, kh, kl, vh, vl};
        for (int idx = tid; idx < 2352; idx += 256) {
            int chunk = idx & 3;
            int row   = (idx >> 2) % 98;
            int mat   = idx / 392;
            int grp   = mat >> 1;
            const __nv_bfloat16* src = (mat & 1) ? Ql : Qh;
            size_t go = ((size_t)b * NTOK + row) * 768 + grp * 256 + h * 32 + chunk * 8;
            CP16(smem_u32(mats[mat] + row * 40 + chunk * 8), src + go);
        }
    }
    CP_COMMIT();
    CP_WAIT0();
    __syncthreads();

    const int wr  = warp * 16;           // 16 rows per warp, 8 warps = 128
    const int sub = lane >> 3, w8 = lane & 7;
    const int r4  = lane >> 2, c2 = (lane & 3) * 2;

    // ---- S = q k^T (scale pre-folded into Wq), bf16x3 ----------------------
    float S[14][4];
    #pragma unroll
    for (int nt = 0; nt < 14; ++nt)
        #pragma unroll
        for (int i = 0; i < 4; ++i) S[nt][i] = 0.f;

    #pragma unroll
    for (int ks = 0; ks < 2; ++ks) {
        uint32_t aqh[4], aql[4];
        {
            int row = wr + w8 + (sub & 1) * 8;
            int col = ks * 16 + (sub >> 1) * 8;
            ldsm_x4(aqh, smem_u32(qh + row * 40 + col));
            ldsm_x4(aql, smem_u32(ql + row * 40 + col));
        }
        #pragma unroll
        for (int nt2 = 0; nt2 < 7; ++nt2) {
            uint32_t bkh[4], bkl[4];
            int row = nt2 * 16 + w8 + (sub & 1) * 8;
            int col = ks * 16 + (sub >> 1) * 8;
            ldsm_x4(bkh, smem_u32(kh + row * 40 + col));
            ldsm_x4(bkl, smem_u32(kl + row * 40 + col));
            mma16816(S[nt2 * 2],     aqh, bkh[0], bkh[2]);
            mma16816(S[nt2 * 2],     aqh, bkl[0], bkl[2]);
            mma16816(S[nt2 * 2],     aql, bkh[0], bkh[2]);
            mma16816(S[nt2 * 2 + 1], aqh, bkh[1], bkh[3]);
            mma16816(S[nt2 * 2 + 1], aqh, bkl[1], bkl[3]);
            mma16816(S[nt2 * 2 + 1], aql, bkh[1], bkh[3]);
        }
    }

    // ---- + (bias+mask) direct from L2, -1e9 padding ------------------------
    const float* slab = g_bm + (size_t)(wi * NHEAD + h) * (NTOK * 100);
    #pragma unroll
    for (int half = 0; half < 2; ++half) {
        int row = wr + r4 + half * 8;
        bool rv = row < NTOK;
        const float* bmrow = slab + (rv ? row : 0) * 100;
        #pragma unroll
        for (int nt = 0; nt < 14; ++nt) {
            int col = nt * 8 + c2;
            float* sp = &S[nt][half * 2];
            if (rv && col < NTOK) {
                float2 bm2 = __ldg((const float2*)(bmrow + col));
                sp[0] += bm2.x;
                sp[1] += bm2.y;
            } else {
                sp[0] = -1e9f;
                sp[1] = -1e9f;
            }
        }
    }

    // ---- softmax in registers (deferred normalization) ---------------------
    float inv_[2];
    #pragma unroll
    for (int half = 0; half < 2; ++half) {
        float mx = -1e30f;
        #pragma unroll
        for (int nt = 0; nt < 14; ++nt)
            mx = fmaxf(mx, fmaxf(S[nt][half * 2], S[nt][half * 2 + 1]));
        mx = fmaxf(mx, __shfl_xor_sync(0xffffffffu, mx, 1));
        mx = fmaxf(mx, __shfl_xor_sync(0xffffffffu, mx, 2));
        float sum = 0.f;
        #pragma unroll
        for (int nt = 0; nt < 14; ++nt) {
            float e0 = fast_exp(S[nt][half * 2]     - mx);
            float e1 = fast_exp(S[nt][half * 2 + 1] - mx);
            S[nt][half * 2]     = e0;
            S[nt][half * 2 + 1] = e1;
            sum += e0 + e1;
        }
        sum += __shfl_xor_sync(0xffffffffu, sum, 1);
        sum += __shfl_xor_sync(0xffffffffu, sum, 2);
        inv_[half] = __fdividef(1.f, sum);
    }

    // ---- O = P @ V (bf16x3) ------------------------------------------------
    float O[4][4];
    #pragma unroll
    for (int nf = 0; nf < 4; ++nf)
        #pragma unroll
        for (int i = 0; i < 4; ++i) O[nf][i] = 0.f;

    #pragma unroll
    for (int kt = 0; kt < 7; ++kt) {
        uint32_t vfh[2][4], vfl[2][4];
        #pragma unroll
        for (int j = 0; j < 2; ++j) {
            int row = kt * 16 + w8 + (sub & 1) * 8;
            int col = j * 16 + (sub >> 1) * 8;
            ldsm_x4t(vfh[j], smem_u32(vh + row * 40 + col));
            ldsm_x4t(vfl[j], smem_u32(vl + row * 40 + col));
        }
        const float* cA = S[2 * kt];
        const float* cB = S[2 * kt + 1];
        uint32_t Ph[4], Pl[4];
        Ph[0] = pack_hi_lo(cA[0], cA[1], &Pl[0]);
        Ph[1] = pack_hi_lo(cA[2], cA[3], &Pl[1]);
        Ph[2] = pack_hi_lo(cB[0], cB[1], &Pl[2]);
        Ph[3] = pack_hi_lo(cB[2], cB[3], &Pl[3]);
        #pragma unroll
        for (int nf = 0; nf < 4; ++nf) {
            uint32_t b0h = vfh[nf >> 1][(nf & 1) * 2];
            uint32_t b1h = vfh[nf >> 1][(nf & 1) * 2 + 1];
            uint32_t b0l = vfl[nf >> 1][(nf & 1) * 2];
            uint32_t b1l = vfl[nf >> 1][(nf & 1) * 2 + 1];
            mma16816(O[nf], Ph, b0h, b1h);
            mma16816(O[nf], Ph, b0l, b1l);
            mma16816(O[nf], Pl, b0h, b1h);
        }
    }

    // ---- store normalized, hi/lo split, vectorized -------------------------
    #pragma unroll
    for (int half = 0; half < 2; ++half) {
        int row = wr + r4 + half * 8;
        if (row < NTOK) {
            float s = inv_[half];
            #pragma unroll
            for (int nf = 0; nf < 4; ++nf) {
                float v0 = O[nf][half * 2]     * s;
                float v1 = O[nf][half * 2 + 1] * s;
                int col = h * 32 + nf * 8 + c2;
                size_t off = ((size_t)b * NTOK + row) * CDIM + col;
                uint32_t lo, hi = pack_hi_lo(v0, v1, &lo);
                *(uint32_t*)(g_ah + off) = hi;
                *(uint32_t*)(g_al + off) = lo;
            }
        }
    }
}

// ===========================================================================
extern "C" void kernel_launch(void* const* d_in, const int* in_sizes, int n_in,
                              void* d_out, int out_size)
{
    const float* x          = (const float*)d_in[0];
    const float* mask       = (const float*)d_in[1];
    const float* qkv_w      = (const float*)d_in[2];
    const float* proj_w     = (const float*)d_in[3];
    const float* proj_b     = (const float*)d_in[4];
    const float* bias_table = (const float*)d_in[5];

    int B  = in_sizes[0] / (NTOK * CDIM);
    int nW = in_sizes[1] / (NTOK * NTOK);
    if (B > MAXB) B = MAXB;
    if (nW > MAXNW) nW = MAXNW;
    const int M = B * NTOK;
    const float scale = 0.17677669529663689f;   // 32^-0.5

    const size_t smem_g = (size_t)STAGE_ELEMS * NSTAGE * sizeof(__nv_bfloat16); // 113664
    const size_t smem_a = 56320;

    cudaFuncSetAttribute(gemm2,  cudaFuncAttributeMaxDynamicSharedMemorySize, (int)smem_g);
    cudaFuncSetAttribute(gemm2b, cudaFuncAttributeMaxDynamicSharedMemorySize, (int)smem_g);
    cudaFuncSetAttribute(attn5,  cudaFuncAttributeMaxDynamicSharedMemorySize, (int)smem_a);

    void* xh_p   = nullptr; cudaGetSymbolAddress(&xh_p,   g_xh);
    void* xl_p   = nullptr; cudaGetSymbolAddress(&xl_p,   g_xl);
    void* qkvh_p = nullptr; cudaGetSymbolAddress(&qkvh_p, g_qkvh);
    void* qkvl_p = nullptr; cudaGetSymbolAddress(&qkvl_p, g_qkvl);
    void* ah_p   = nullptr; cudaGetSymbolAddress(&ah_p,   g_ah);
    void* al_p   = nullptr; cudaGetSymbolAddress(&al_p,   g_al);
    void* wqh_p  = nullptr; cudaGetSymbolAddress(&wqh_p,  g_wqh);
    void* wql_p  = nullptr; cudaGetSymbolAddress(&wql_p,  g_wql);
    void* wph_p  = nullptr; cudaGetSymbolAddress(&wph_p,  g_wph);
    void* wpl_p  = nullptr; cudaGetSymbolAddress(&wpl_p,  g_wpl);

    // input/weight splits (q-scale folded into Wq columns 0..255)
    {
        int n4 = M * CDIM / 4;
        convert_split<<<(n4 + 255) / 256, 256>>>(x, (__nv_bfloat16*)xh_p,
                                                 (__nv_bfloat16*)xl_p, n4, 64, 0, 1.f);
        int w1 = CDIM * 3 * CDIM / 4;
        convert_split<<<(w1 + 255) / 256, 256>>>(qkv_w, (__nv_bfloat16*)wqh_p,
                                                 (__nv_bfloat16*)wql_p, w1, 192, 64, scale);
        int w2 = CDIM * CDIM / 4;
        convert_split<<<(w2 + 255) / 256, 256>>>(proj_w, (__nv_bfloat16*)wph_p,
                                                 (__nv_bfloat16*)wpl_p, w2, 64, 0, 1.f);
        int nbm = nW * NHEAD * NTOK * 100;
        prep_bm<<<(nbm + 255) / 256, 256>>>(mask, bias_table, nW);
    }

    dim3 g1((M + BM - 1) / BM, (3 * CDIM) / BN);   // 1568 x 6
    gemm2b<<<g1, 256, smem_g>>>((__nv_bfloat16*)xh_p, (__nv_bfloat16*)xl_p,
                                (__nv_bfloat16*)wqh_p, (__nv_bfloat16*)wql_p,
                                (__nv_bfloat16*)qkvh_p, (__nv_bfloat16*)qkvl_p,
                                M, 3 * CDIM);

    attn5<<<B * NHEAD, 256, smem_a>>>((__nv_bfloat16*)qkvh_p,
                                      (__nv_bfloat16*)qkvl_p, nW);

    dim3 g2d((M + BM - 1) / BM, CDIM / BN);        // 1568 x 2
    gemm2<<<g2d, 256, smem_g>>>((__nv_bfloat16*)ah_p, (__nv_bfloat16*)al_p,
                                (__nv_bfloat16*)wph_p, (__nv_bfloat16*)wpl_p,
                                proj_b, (float*)d_out, M, CDIM);
}